// round 2
// baseline (speedup 1.0000x reference)
#include <cuda_runtime.h>
#include <math.h>

#define BATCH 32
#define NTOK  1024
#define CDIM  4096
#define HDIM  2048
#define DDIM  64
#define TTOT  (BATCH*NTOK)   /* 32768 tokens */

typedef unsigned long long ull;

// ---------------- scratch (device globals; no allocation) ----------------
__device__ float g_ww1[CDIM*DDIM];          // ln_w[c]*w1[c,d]            (1 MB)
__device__ float g_csp[16][2][DDIM];        // column-sum partials
__device__ float g_cs[4][DDIM];             // 0:colsum_lo 1:cb_lo 2:colsum_hi 3:cb_hi
__device__ float g_S[(size_t)TTOT*DDIM];    // lower-half GEMM result     (8 MB)
__device__ float g_s1[TTOT];                // lower-half sum x
__device__ float g_s2[TTOT];                // lower-half sum x^2
__device__ float g_mu[TTOT];
__device__ float g_r[TTOT];
__device__ float g_Ap[(size_t)BATCH*64*HDIM]; // deterministic A partials (16 MB)
__device__ float g_A[BATCH*HDIM];
__device__ float g_gf[BATCH*DDIM];          // g + cb_lo + b1 folded

// ---- f32x2 helpers -------------------------------------------------------
__device__ __forceinline__ ull pack_dup(float v) {
    ull r; asm("mov.b64 %0, {%1, %1};" : "=l"(r) : "f"(v)); return r;
}
__device__ __forceinline__ ull ffma2(ull a, ull b, ull c) {
    ull d; asm("fma.rn.f32x2 %0, %1, %2, %3;" : "=l"(d) : "l"(a), "l"(b), "l"(c)); return d;
}
__device__ __forceinline__ void unpack2(ull v, float& lo, float& hi) {
    asm("mov.b64 {%0, %1}, %2;" : "=f"(lo), "=f"(hi) : "l"(v));
}
__device__ __forceinline__ void lds_v2_u64(unsigned addr, ull& a, ull& b) {
    asm volatile("ld.shared.v2.u64 {%0, %1}, [%2];" : "=l"(a), "=l"(b) : "r"(addr));
}

// ---------------- k_prep: ww1 = ln_w * w1 ----------------
__global__ void k_prep(const float* __restrict__ ln_w, const float* __restrict__ w1) {
    for (int i = blockIdx.x*blockDim.x + threadIdx.x; i < CDIM*DDIM; i += gridDim.x*blockDim.x)
        g_ww1[i] = ln_w[i >> 6] * w1[i];
}

// ---------------- k_cs: column sums of ln_w*w1 and ln_b*w1, per half ----------------
__global__ void k_cs(const float* __restrict__ ln_w, const float* __restrict__ ln_b,
                     const float* __restrict__ w1) {
    __shared__ float red[4][2][DDIM];
    int d = threadIdx.x & 63, s = threadIdx.x >> 6;
    int c0 = (blockIdx.x*4 + s) * 64;
    float a0 = 0.f, a1 = 0.f;
    for (int cc = 0; cc < 64; cc++) {
        int c = c0 + cc;
        float wv = w1[c*DDIM + d];
        a0 += ln_w[c]*wv;
        a1 += ln_b[c]*wv;
    }
    red[s][0][d] = a0; red[s][1][d] = a1;
    __syncthreads();
    if (threadIdx.x < 128) {
        int which = threadIdx.x >> 6, dd = threadIdx.x & 63;
        g_csp[blockIdx.x][which][dd] =
            red[0][which][dd] + red[1][which][dd] + red[2][which][dd] + red[3][which][dd];
    }
}

__global__ void k_red(void) {
    int o = threadIdx.x >> 6, d = threadIdx.x & 63;
    int base = (o >= 2) ? 8 : 0;
    int which = o & 1;
    float s = 0.f;
    #pragma unroll
    for (int bi = 0; bi < 8; bi++) s += g_csp[base + bi][which][d];
    g_cs[o][d] = s;
}

// ---------------- k_main: S[t,d] = sum_{c<2048} x[t,c]*ww1[c,d]  + lower moments --------
// CTA tile: 128 tokens x 64 d, k-tile 32. xs stored TRANSPOSED [k][token] so adjacent
// tokens form natural f32x2 pairs. Thread tile: 8 tokens (4 pairs) x 4 d via fma.rn.f32x2.
#define KT 32
#define XPITCH 132
__global__ void __launch_bounds__(256) k_main(const float* __restrict__ x) {
    __shared__ __align__(16) float xs[KT][XPITCH];   // [k][token 0..127]
    __shared__ __align__(16) float ws[KT][64];       // [k][d]
    __shared__ float red[2][2][128];
    int tid = threadIdx.x;
    int t0  = blockIdx.x * 128;
    int ty = tid >> 4, tx = tid & 15;                // 16x16: 8 tok x 4 d each
    int ts = tid & 127, sh = (tid >> 7) * 16;        // stats: token ts, k-slice sh..sh+15

    ull acc[4][4];
    #pragma unroll
    for (int i = 0; i < 4; i++)
        #pragma unroll
        for (int j = 0; j < 4; j++) acc[i][j] = 0ULL;
    float s1 = 0.f, s2 = 0.f;

    unsigned xs_base = (unsigned)__cvta_generic_to_shared(&xs[0][0]);

    for (int cc = 0; cc < HDIM; cc += KT) {
        // load x tile transposed: 128 tok x 32 k = 1024 float4 (4 per thread)
        #pragma unroll
        for (int l = 0; l < 4; l++) {
            int idx = tid + l*256;
            int tok = idx & 127, kq = idx >> 7;      // kq in 0..7 (groups of 4 k)
            float4 v = *(const float4*)(x + (size_t)(t0 + tok)*CDIM + cc + 4*kq);
            xs[4*kq + 0][tok] = v.x;
            xs[4*kq + 1][tok] = v.y;
            xs[4*kq + 2][tok] = v.z;
            xs[4*kq + 3][tok] = v.w;
        }
        // load weights: 32 x 64 = 512 float4 (2 per thread)
        #pragma unroll
        for (int l = 0; l < 2; l++) {
            int idx = tid + l*256;
            int kr = idx >> 4, q = idx & 15;
            *(float4*)&ws[kr][4*q] = *(const float4*)(g_ww1 + (size_t)(cc + kr)*DDIM + 4*q);
        }
        __syncthreads();
        // lower-half moments
        #pragma unroll
        for (int kk = 0; kk < 16; kk++) {
            float v = xs[sh + kk][ts];
            s1 += v; s2 += v*v;
        }
        // GEMM: token-paired f32x2
        #pragma unroll 8
        for (int k = 0; k < KT; k++) {
            ull a0, a1, a2, a3;
            unsigned arow = xs_base + (unsigned)(k*XPITCH + 8*ty)*4u;
            lds_v2_u64(arow,       a0, a1);          // tokens 8ty+0..3 as 2 pairs
            lds_v2_u64(arow + 16u, a2, a3);          // tokens 8ty+4..7 as 2 pairs
            float4 b4 = *(const float4*)&ws[k][4*tx];
            ull b0 = pack_dup(b4.x), b1 = pack_dup(b4.y);
            ull b2 = pack_dup(b4.z), b3 = pack_dup(b4.w);
            acc[0][0] = ffma2(a0, b0, acc[0][0]);
            acc[0][1] = ffma2(a0, b1, acc[0][1]);
            acc[0][2] = ffma2(a0, b2, acc[0][2]);
            acc[0][3] = ffma2(a0, b3, acc[0][3]);
            acc[1][0] = ffma2(a1, b0, acc[1][0]);
            acc[1][1] = ffma2(a1, b1, acc[1][1]);
            acc[1][2] = ffma2(a1, b2, acc[1][2]);
            acc[1][3] = ffma2(a1, b3, acc[1][3]);
            acc[2][0] = ffma2(a2, b0, acc[2][0]);
            acc[2][1] = ffma2(a2, b1, acc[2][1]);
            acc[2][2] = ffma2(a2, b2, acc[2][2]);
            acc[2][3] = ffma2(a2, b3, acc[2][3]);
            acc[3][0] = ffma2(a3, b0, acc[3][0]);
            acc[3][1] = ffma2(a3, b1, acc[3][1]);
            acc[3][2] = ffma2(a3, b2, acc[3][2]);
            acc[3][3] = ffma2(a3, b3, acc[3][3]);
        }
        __syncthreads();
    }
    // write S: each acc pair holds {token 8ty+2h, token 8ty+2h+1} for d = 4tx+j
    #pragma unroll
    for (int h = 0; h < 4; h++) {
        float lo0, hi0, lo1, hi1, lo2, hi2, lo3, hi3;
        unpack2(acc[h][0], lo0, hi0);
        unpack2(acc[h][1], lo1, hi1);
        unpack2(acc[h][2], lo2, hi2);
        unpack2(acc[h][3], lo3, hi3);
        int tA = t0 + 8*ty + 2*h;
        *(float4*)(g_S + (size_t)tA*DDIM + 4*tx)     = make_float4(lo0, lo1, lo2, lo3);
        *(float4*)(g_S + (size_t)(tA+1)*DDIM + 4*tx) = make_float4(hi0, hi1, hi2, hi3);
    }
    red[0][tid >> 7][ts] = s1;
    red[1][tid >> 7][ts] = s2;
    __syncthreads();
    if (tid < 128) {
        g_s1[t0 + tid] = red[0][0][tid] + red[0][1][tid];
        g_s2[t0 + tid] = red[1][0][tid] + red[1][1][tid];
    }
}

// ---------------- k_upper: finalize mu,r; A partials over upper half ----------------
__global__ void __launch_bounds__(256) k_upper(const float* __restrict__ x) {
    extern __shared__ float xu[];               // [16][2048] = 128 KB
    __shared__ float rr[16];
    int tid = threadIdx.x;
    int t0 = blockIdx.x * 16;
    int b  = t0 >> 10;

    const float4* X4 = (const float4*)x;
    float4* xu4 = (float4*)xu;
    #pragma unroll
    for (int l = 0; l < 32; l++) {
        int idx = tid + l*256;
        int r = idx >> 9, q = idx & 511;
        xu4[r*512 + q] = X4[(size_t)(t0 + r)*1024 + 512 + q];
    }
    __syncthreads();

    int w = tid >> 5, lane = tid & 31;
    #pragma unroll
    for (int rep = 0; rep < 2; rep++) {
        int tok = w*2 + rep;
        float s1 = 0.f, s2 = 0.f;
        #pragma unroll 8
        for (int k = 0; k < 64; k++) {
            float v = xu[tok*2048 + lane + 32*k];
            s1 += v; s2 += v*v;
        }
        #pragma unroll
        for (int o = 16; o > 0; o >>= 1) {
            s1 += __shfl_down_sync(0xffffffffu, s1, o);
            s2 += __shfl_down_sync(0xffffffffu, s2, o);
        }
        if (lane == 0) {
            int t = t0 + tok;
            float S1 = g_s1[t] + s1;
            float S2 = g_s2[t] + s2;
            float mu  = S1 * (1.0f/4096.0f);
            float var = S2 * (1.0f/4096.0f) - mu*mu;
            float rv  = rsqrtf(var + 1e-5f);
            g_mu[t] = mu; g_r[t] = rv; rr[tok] = rv;
        }
    }
    __syncthreads();

    int cib = blockIdx.x & 63;
    float* Ap = g_Ap + (size_t)(b*64 + cib)*HDIM;
    #pragma unroll
    for (int m = 0; m < 8; m++) {
        int j = tid + m*256;
        float acc = 0.f;
        #pragma unroll
        for (int t = 0; t < 16; t++) acc += xu[t*2048 + j] * rr[t];
        Ap[j] = acc;
    }
}

// ---------------- k_redA: reduce 64 partials -> A (includes 1/N) ----------------
__global__ void k_redA(void) {
    int i = blockIdx.x*blockDim.x + threadIdx.x;
    int b = i >> 11, j = i & 2047;
    float s = 0.f;
    #pragma unroll 8
    for (int p = 0; p < 64; p++) s += g_Ap[(size_t)(b*64 + p)*HDIM + j];
    g_A[i] = s * (1.0f/1024.0f);
}

// ---------------- k_g: per-batch global contribution (+ fold cb_lo + b1) ----------------
__global__ void k_g(const float* __restrict__ b1) {
    __shared__ float red[4][64];
    __shared__ float mred[256];
    int b = blockIdx.x, tid = threadIdx.x;
    float m = 0.f;
    #pragma unroll
    for (int k = 0; k < 4; k++) {
        int t = b*1024 + tid + k*256;
        m += g_mu[t] * g_r[t];
    }
    mred[tid] = m;
    __syncthreads();
    for (int o = 128; o > 0; o >>= 1) {
        if (tid < o) mred[tid] += mred[tid + o];
        __syncthreads();
    }
    float m_b = mred[0] * (1.0f/1024.0f);

    int d = tid & 63, s = tid >> 6;
    float acc = 0.f;
    const float* A = g_A + b*HDIM;
    for (int jj = 0; jj < 512; jj++) {
        int j = s*512 + jj;
        acc += g_ww1[(size_t)(HDIM + j)*DDIM + d] * A[j];
    }
    red[s][d] = acc;
    __syncthreads();
    if (tid < 64) {
        float g = red[0][tid] + red[1][tid] + red[2][tid] + red[3][tid];
        g_gf[b*DDIM + tid] = g - m_b*g_cs[2][tid] + g_cs[3][tid] + g_cs[1][tid] + b1[tid];
    }
}

// ---------------- k_epi: gate decision + out = x * keep ----------------
__global__ void __launch_bounds__(256) k_epi(const float* __restrict__ x,
                                             const float* __restrict__ gum,
                                             const float* __restrict__ w2,
                                             const float* __restrict__ b2,
                                             float* __restrict__ out) {
    __shared__ float keep[8];
    int tid = threadIdx.x, w = tid >> 5, lane = tid & 31;
    int t0 = blockIdx.x * 8;
    int t  = t0 + w;
    int b  = t >> 10;
    float mu = g_mu[t], rv = g_r[t];
    float l0 = 0.f, l1 = 0.f;
    #pragma unroll
    for (int p = 0; p < 2; p++) {
        int d = lane + 32*p;
        float sv = g_S[(size_t)t*DDIM + d];
        float h  = rv*(sv - mu*g_cs[0][d]) + g_gf[b*DDIM + d];
        float ge = 0.5f*h*(1.0f + erff(h*0.70710678118654752f));
        l0 += ge * w2[d*2 + 0];
        l1 += ge * w2[d*2 + 1];
    }
    #pragma unroll
    for (int o = 16; o > 0; o >>= 1) {
        l0 += __shfl_down_sync(0xffffffffu, l0, o);
        l1 += __shfl_down_sync(0xffffffffu, l1, o);
    }
    if (lane == 0) {
        l0 += b2[0] + gum[t*2 + 0];
        l1 += b2[1] + gum[t*2 + 1];
        keep[w] = (l0 >= l1) ? 1.0f : 0.0f;
    }
    __syncthreads();
    const float4* X4 = (const float4*)x;
    float4* O4 = (float4*)out;
    #pragma unroll
    for (int l = 0; l < 32; l++) {
        int idx = tid + l*256;
        int r = idx >> 10, q = idx & 1023;
        float kv = keep[r];
        float4 v = X4[(size_t)(t0 + r)*1024 + q];
        v.x *= kv; v.y *= kv; v.z *= kv; v.w *= kv;
        O4[(size_t)(t0 + r)*1024 + q] = v;
    }
}

// ---------------- launch ----------------
extern "C" void kernel_launch(void* const* d_in, const int* in_sizes, int n_in,
                              void* d_out, int out_size) {
    const float* x    = (const float*)d_in[0];
    const float* gum  = (const float*)d_in[1];
    const float* ln_w = (const float*)d_in[2];
    const float* ln_b = (const float*)d_in[3];
    const float* w1   = (const float*)d_in[4];
    const float* b1   = (const float*)d_in[5];
    const float* w2   = (const float*)d_in[6];
    const float* b2   = (const float*)d_in[7];
    float* out = (float*)d_out;

    cudaFuncSetAttribute(k_upper, cudaFuncAttributeMaxDynamicSharedMemorySize, 16*2048*4);

    k_prep<<<256, 256>>>(ln_w, w1);
    k_cs  <<<16, 256>>>(ln_w, ln_b, w1);
    k_red <<<1, 256>>>();
    k_main<<<TTOT/128, 256>>>(x);
    k_upper<<<TTOT/16, 256, 16*2048*4>>>(x);
    k_redA<<<256, 256>>>();
    k_g   <<<BATCH, 256>>>(b1);
    k_epi <<<TTOT/8, 256>>>(x, gum, w2, b2, out);
}

// round 6
// speedup vs baseline: 1.3935x; 1.3935x over previous
#include <cuda_runtime.h>
#include <cuda_fp16.h>
#include <cstdint>
#include <math.h>

#define BATCH 32
#define NTOK  1024
#define CDIM  4096
#define HDIM  2048
#define DDIM  64
#define TTOT  (BATCH*NTOK)   /* 32768 tokens */

// ---------------- scratch (device globals; no allocation) ----------------
__device__ float g_ww1[CDIM*DDIM];          // ln_w[c]*w1[c,d]            (1 MB)
__device__ float g_csp[16][2][DDIM];
__device__ float g_cs[4][DDIM];             // 0:colsum_lo 1:cb_lo 2:colsum_hi 3:cb_hi
__device__ float g_S[(size_t)TTOT*DDIM];    // lower-half GEMM result     (8 MB)
__device__ float g_s1[TTOT];
__device__ float g_s2[TTOT];
__device__ float g_mu[TTOT];
__device__ float g_r[TTOT];
__device__ float g_Ap[(size_t)BATCH*64*HDIM];
__device__ float g_A[BATCH*HDIM];
__device__ float g_gf[BATCH*DDIM];
// B fragments pre-packed in per-lane mma order:
// [kstep 0..127][n8blk 0..7][lane 0..31][4] = {hi_r0, hi_r1, lo_r0, lo_r1}  (512 KB)
__device__ uint32_t g_Bfrag[128*8*32*4];

// ---- mma.sync m16n8k16 fp16 -> f32 (sm_80+, valid on plain sm_100) ----
__device__ __forceinline__ void mma16816(float* c, const uint32_t* a,
                                         uint32_t b0, uint32_t b1) {
    asm volatile("mma.sync.aligned.m16n8k16.row.col.f32.f16.f16.f32 "
        "{%0,%1,%2,%3}, {%4,%5,%6,%7}, {%8,%9}, {%0,%1,%2,%3};"
        : "+f"(c[0]), "+f"(c[1]), "+f"(c[2]), "+f"(c[3])
        : "r"(a[0]), "r"(a[1]), "r"(a[2]), "r"(a[3]), "r"(b0), "r"(b1));
}
__device__ __forceinline__ uint32_t h2u(__half2 h) {
    return *reinterpret_cast<uint32_t*>(&h);
}

// ---------------- k_prep: ww1 = ln_w * w1 ----------------
__global__ void k_prep(const float* __restrict__ ln_w, const float* __restrict__ w1) {
    for (int i = blockIdx.x*blockDim.x + threadIdx.x; i < CDIM*DDIM; i += gridDim.x*blockDim.x)
        g_ww1[i] = ln_w[i >> 6] * w1[i];
}

// ---------------- k_prep_b: split weights to fp16 hi/lo, pack in fragment order ----
__global__ void k_prep_b(void) {
    int i = blockIdx.x*blockDim.x + threadIdx.x;     // 128*8*32 = 32768
    if (i >= 128*8*32) return;
    int ks = i >> 8, blk = (i >> 5) & 7, lane = i & 31;
    int t = lane & 3, g = lane >> 2;
    int n = blk*8 + g;
    int k0 = ks*16 + 2*t;
    float wa = g_ww1[(size_t)(k0    )*DDIM + n];
    float wb = g_ww1[(size_t)(k0 + 1)*DDIM + n];
    float wc = g_ww1[(size_t)(k0 + 8)*DDIM + n];
    float wd = g_ww1[(size_t)(k0 + 9)*DDIM + n];
    __half2 hiA = __floats2half2_rn(wa, wb);
    __half2 hiB = __floats2half2_rn(wc, wd);
    float2 fA = __half22float2(hiA), fB = __half22float2(hiB);
    __half2 loA = __floats2half2_rn(wa - fA.x, wb - fA.y);
    __half2 loB = __floats2half2_rn(wc - fB.x, wd - fB.y);
    uint4 v = make_uint4(h2u(hiA), h2u(hiB), h2u(loA), h2u(loB));
    *reinterpret_cast<uint4*>(g_Bfrag + (size_t)i*4) = v;
}

// ---------------- k_cs / k_red ----------------
__global__ void k_cs(const float* __restrict__ ln_w, const float* __restrict__ ln_b,
                     const float* __restrict__ w1) {
    __shared__ float red[4][2][DDIM];
    int d = threadIdx.x & 63, s = threadIdx.x >> 6;
    int c0 = (blockIdx.x*4 + s) * 64;
    float a0 = 0.f, a1 = 0.f;
    for (int cc = 0; cc < 64; cc++) {
        int c = c0 + cc;
        float wv = w1[c*DDIM + d];
        a0 += ln_w[c]*wv;
        a1 += ln_b[c]*wv;
    }
    red[s][0][d] = a0; red[s][1][d] = a1;
    __syncthreads();
    if (threadIdx.x < 128) {
        int which = threadIdx.x >> 6, dd = threadIdx.x & 63;
        g_csp[blockIdx.x][which][dd] =
            red[0][which][dd] + red[1][which][dd] + red[2][which][dd] + red[3][which][dd];
    }
}
__global__ void k_red(void) {
    int o = threadIdx.x >> 6, d = threadIdx.x & 63;
    int base = (o >= 2) ? 8 : 0;
    int which = o & 1;
    float s = 0.f;
    #pragma unroll
    for (int bi = 0; bi < 8; bi++) s += g_csp[base + bi][which][d];
    g_cs[o][d] = s;
}

// ---------------- k_main_mma: fp16 3-term split GEMM via mma.sync + lower moments ----
// CTA: 128 tokens x 64 d; 8 warps in 4(M) x 2(N) grid, warp tile 32 tok x 32 d.
// No smem, no __syncthreads in the hot loop. A fragments loaded straight from gmem.
__global__ void __launch_bounds__(256) k_main_mma(const float* __restrict__ x) {
    int tid = threadIdx.x, wid = tid >> 5, lane = tid & 31;
    int mi = wid >> 1, nj = wid & 1;
    int t0 = blockIdx.x * 128;
    int tbase = t0 + mi*32;               // warp's token base
    int g = lane >> 2, t = lane & 3;

    // 4 row pointers for this lane (rows g, g+8, g+16, g+24), at col 2t
    const float* xr[4];
    #pragma unroll
    for (int r = 0; r < 4; r++)
        xr[r] = x + (size_t)(tbase + g + r*8)*CDIM + 2*t;

    const uint4* Bf = reinterpret_cast<const uint4*>(g_Bfrag) + (size_t)(4*nj)*32 + lane;

    float acc[2][4][4];
    #pragma unroll
    for (int s = 0; s < 2; s++)
        #pragma unroll
        for (int j = 0; j < 4; j++)
            #pragma unroll
            for (int q = 0; q < 4; q++) acc[s][j][q] = 0.f;
    float m1[4] = {0.f,0.f,0.f,0.f}, m2[4] = {0.f,0.f,0.f,0.f};

    #pragma unroll 2
    for (int ks = 0; ks < 128; ks++) {
        // ---- load A elements (this lane's fragment positions) ----
        float2 xa[4][2];
        #pragma unroll
        for (int r = 0; r < 4; r++) {
            xa[r][0] = *reinterpret_cast<const float2*>(xr[r] + ks*16);
            xa[r][1] = *reinterpret_cast<const float2*>(xr[r] + ks*16 + 8);
        }
        // ---- moments (nj==0 warps only; each element owned by exactly one lane) ----
        if (nj == 0) {
            #pragma unroll
            for (int r = 0; r < 4; r++) {
                m1[r] += xa[r][0].x + xa[r][0].y + xa[r][1].x + xa[r][1].y;
                m2[r] = fmaf(xa[r][0].x, xa[r][0].x, m2[r]);
                m2[r] = fmaf(xa[r][0].y, xa[r][0].y, m2[r]);
                m2[r] = fmaf(xa[r][1].x, xa[r][1].x, m2[r]);
                m2[r] = fmaf(xa[r][1].y, xa[r][1].y, m2[r]);
            }
        }
        // ---- split to fp16 hi/lo fragments ----
        // A frag regs for m16 tile s (rows pair 2s, 2s+1): {row lo-cols, row+8 lo-cols, row hi-cols, row+8 hi-cols}
        uint32_t ahi[2][4], alo[2][4];
        #pragma unroll
        for (int s = 0; s < 2; s++) {
            #pragma unroll
            for (int h = 0; h < 2; h++) {            // h=0: cols 2t, h=1: cols 2t+8
                #pragma unroll
                for (int rr = 0; rr < 2; rr++) {     // rr=0: row g, rr=1: row g+8
                    float2 v = xa[2*s + rr][h];
                    __half2 hi = __floats2half2_rn(v.x, v.y);
                    float2 hf = __half22float2(hi);
                    __half2 lo = __floats2half2_rn(v.x - hf.x, v.y - hf.y);
                    ahi[s][h*2 + rr] = h2u(hi);
                    alo[s][h*2 + rr] = h2u(lo);
                }
            }
        }
        // ---- load B fragments (pre-packed, coalesced LDG.128) ----
        uint4 bf[4];
        #pragma unroll
        for (int j = 0; j < 4; j++)
            bf[j] = Bf[(size_t)(ks*8 + j)*32];
        // ---- 3-term mma ----
        #pragma unroll
        for (int s = 0; s < 2; s++) {
            #pragma unroll
            for (int j = 0; j < 4; j++) {
                mma16816(acc[s][j], ahi[s], bf[j].x, bf[j].y);   // hi*hi
                mma16816(acc[s][j], ahi[s], bf[j].z, bf[j].w);   // hi*lo
                mma16816(acc[s][j], alo[s], bf[j].x, bf[j].y);   // lo*hi
            }
        }
    }

    // ---- moments reduction over the 4 k-col lanes (t bits) ----
    if (nj == 0) {
        #pragma unroll
        for (int r = 0; r < 4; r++) {
            m1[r] += __shfl_xor_sync(0xffffffffu, m1[r], 1);
            m1[r] += __shfl_xor_sync(0xffffffffu, m1[r], 2);
            m2[r] += __shfl_xor_sync(0xffffffffu, m2[r], 1);
            m2[r] += __shfl_xor_sync(0xffffffffu, m2[r], 2);
        }
        if (t == 0) {
            #pragma unroll
            for (int r = 0; r < 4; r++) {
                g_s1[tbase + g + r*8] = m1[r];
                g_s2[tbase + g + r*8] = m2[r];
            }
        }
    }

    // ---- store S fragments ----
    int d0 = nj*32;
    #pragma unroll
    for (int s = 0; s < 2; s++) {
        #pragma unroll
        for (int j = 0; j < 4; j++) {
            int row = tbase + s*16 + g;
            int d = d0 + j*8 + 2*t;
            *reinterpret_cast<float2*>(g_S + (size_t)row*DDIM + d) =
                make_float2(acc[s][j][0], acc[s][j][1]);
            *reinterpret_cast<float2*>(g_S + (size_t)(row + 8)*DDIM + d) =
                make_float2(acc[s][j][2], acc[s][j][3]);
        }
    }
}

// ---------------- k_upper: finalize mu,r; A partials over upper half ----------------
__global__ void __launch_bounds__(256) k_upper(const float* __restrict__ x) {
    extern __shared__ float xu[];               // [16][2048] = 128 KB
    __shared__ float rr[16];
    int tid = threadIdx.x;
    int t0 = blockIdx.x * 16;
    int b  = t0 >> 10;

    const float4* X4 = (const float4*)x;
    float4* xu4 = (float4*)xu;
    #pragma unroll
    for (int l = 0; l < 32; l++) {
        int idx = tid + l*256;
        int r = idx >> 9, q = idx & 511;
        xu4[r*512 + q] = X4[(size_t)(t0 + r)*1024 + 512 + q];
    }
    __syncthreads();

    int w = tid >> 5, lane = tid & 31;
    #pragma unroll
    for (int rep = 0; rep < 2; rep++) {
        int tok = w*2 + rep;
        float s1 = 0.f, s2 = 0.f;
        #pragma unroll 8
        for (int k = 0; k < 64; k++) {
            float v = xu[tok*2048 + lane + 32*k];
            s1 += v; s2 += v*v;
        }
        #pragma unroll
        for (int o = 16; o > 0; o >>= 1) {
            s1 += __shfl_down_sync(0xffffffffu, s1, o);
            s2 += __shfl_down_sync(0xffffffffu, s2, o);
        }
        if (lane == 0) {
            int tk = t0 + tok;
            float S1 = g_s1[tk] + s1;
            float S2 = g_s2[tk] + s2;
            float mu  = S1 * (1.0f/4096.0f);
            float var = S2 * (1.0f/4096.0f) - mu*mu;
            float rv  = rsqrtf(var + 1e-5f);
            g_mu[tk] = mu; g_r[tk] = rv; rr[tok] = rv;
        }
    }
    __syncthreads();

    int cib = blockIdx.x & 63;
    float* Ap = g_Ap + (size_t)(b*64 + cib)*HDIM;
    #pragma unroll
    for (int m = 0; m < 8; m++) {
        int j = tid + m*256;
        float acc = 0.f;
        #pragma unroll
        for (int tt = 0; tt < 16; tt++) acc += xu[tt*2048 + j] * rr[tt];
        Ap[j] = acc;
    }
}

// ---------------- k_redA ----------------
__global__ void k_redA(void) {
    int i = blockIdx.x*blockDim.x + threadIdx.x;
    int b = i >> 11, j = i & 2047;
    float s = 0.f;
    #pragma unroll 8
    for (int p = 0; p < 64; p++) s += g_Ap[(size_t)(b*64 + p)*HDIM + j];
    g_A[i] = s * (1.0f/1024.0f);
}

// ---------------- k_g ----------------
__global__ void k_g(const float* __restrict__ b1) {
    __shared__ float red[4][64];
    __shared__ float mred[256];
    int b = blockIdx.x, tid = threadIdx.x;
    float m = 0.f;
    #pragma unroll
    for (int k = 0; k < 4; k++) {
        int tk = b*1024 + tid + k*256;
        m += g_mu[tk] * g_r[tk];
    }
    mred[tid] = m;
    __syncthreads();
    for (int o = 128; o > 0; o >>= 1) {
        if (tid < o) mred[tid] += mred[tid + o];
        __syncthreads();
    }
    float m_b = mred[0] * (1.0f/1024.0f);

    int d = tid & 63, s = tid >> 6;
    float acc = 0.f;
    const float* A = g_A + b*HDIM;
    for (int jj = 0; jj < 512; jj++) {
        int j = s*512 + jj;
        acc += g_ww1[(size_t)(HDIM + j)*DDIM + d] * A[j];
    }
    red[s][d] = acc;
    __syncthreads();
    if (tid < 64) {
        float g = red[0][tid] + red[1][tid] + red[2][tid] + red[3][tid];
        g_gf[b*DDIM + tid] = g - m_b*g_cs[2][tid] + g_cs[3][tid] + g_cs[1][tid] + b1[tid];
    }
}

// ---------------- k_epi ----------------
__global__ void __launch_bounds__(256) k_epi(const float* __restrict__ x,
                                             const float* __restrict__ gum,
                                             const float* __restrict__ w2,
                                             const float* __restrict__ b2,
                                             float* __restrict__ out) {
    __shared__ float keep[8];
    int tid = threadIdx.x, w = tid >> 5, lane = tid & 31;
    int t0 = blockIdx.x * 8;
    int tk = t0 + w;
    int b  = tk >> 10;
    float mu = g_mu[tk], rv = g_r[tk];
    float l0 = 0.f, l1 = 0.f;
    #pragma unroll
    for (int p = 0; p < 2; p++) {
        int d = lane + 32*p;
        float sv = g_S[(size_t)tk*DDIM + d];
        float h  = rv*(sv - mu*g_cs[0][d]) + g_gf[b*DDIM + d];
        float ge = 0.5f*h*(1.0f + erff(h*0.70710678118654752f));
        l0 += ge * w2[d*2 + 0];
        l1 += ge * w2[d*2 + 1];
    }
    #pragma unroll
    for (int o = 16; o > 0; o >>= 1) {
        l0 += __shfl_down_sync(0xffffffffu, l0, o);
        l1 += __shfl_down_sync(0xffffffffu, l1, o);
    }
    if (lane == 0) {
        l0 += b2[0] + gum[tk*2 + 0];
        l1 += b2[1] + gum[tk*2 + 1];
        keep[w] = (l0 >= l1) ? 1.0f : 0.0f;
    }
    __syncthreads();
    const float4* X4 = (const float4*)x;
    float4* O4 = (float4*)out;
    #pragma unroll
    for (int l = 0; l < 32; l++) {
        int idx = tid + l*256;
        int r = idx >> 10, q = idx & 1023;
        float kv = keep[r];
        float4 v = X4[(size_t)(t0 + r)*1024 + q];
        v.x *= kv; v.y *= kv; v.z *= kv; v.w *= kv;
        O4[(size_t)(t0 + r)*1024 + q] = v;
    }
}

// ---------------- launch ----------------
extern "C" void kernel_launch(void* const* d_in, const int* in_sizes, int n_in,
                              void* d_out, int out_size) {
    const float* x    = (const float*)d_in[0];
    const float* gum  = (const float*)d_in[1];
    const float* ln_w = (const float*)d_in[2];
    const float* ln_b = (const float*)d_in[3];
    const float* w1   = (const float*)d_in[4];
    const float* b1   = (const float*)d_in[5];
    const float* w2   = (const float*)d_in[6];
    const float* b2   = (const float*)d_in[7];
    float* out = (float*)d_out;

    cudaFuncSetAttribute(k_upper, cudaFuncAttributeMaxDynamicSharedMemorySize, 16*2048*4);

    k_prep   <<<256, 256>>>(ln_w, w1);
    k_prep_b <<<128, 256>>>();
    k_cs     <<<16, 256>>>(ln_w, ln_b, w1);
    k_red    <<<1, 256>>>();
    k_main_mma<<<TTOT/128, 256>>>(x);
    k_upper  <<<TTOT/16, 256, 16*2048*4>>>(x);
    k_redA   <<<256, 256>>>();
    k_g      <<<BATCH, 256>>>(b1);
    k_epi    <<<TTOT/8, 256>>>(x, gum, w2, b2, out);
}